// round 17
// baseline (speedup 1.0000x reference)
#include <cuda_runtime.h>
#include <math.h>

// SmoothLDDTLoss — B=2, N=4096.
//
// c_lm in the reference contains (nuc | ~nuc) == True -> c_lm == ~eye(N);
// is_dna/is_rna are dead inputs.
//   loss = 1 - [ sum_{l!=m} 0.25*(sig(.5-d)+sig(1-d)+sig(2-d)+sig(4-d)) ] / (B*N*(N-1))
//   d = | ||xGT_l-xGT_m||^2 - ||x_l-x_m||^2 |
//
// u = exp(-d) in (0,1]:  Q(u) = 1 + s1 u + s2 u^2 + s3 u^3 + s4 u^4,
//   sum_i sig(c_i - d) = u * Q'(u) / Q(u)     (1 EX2 + 1 RCP per pair)
//
// Triangular 128x128 tiles, unmasked + analytic diagonal correction:
//   sum_{l!=m} = 2*Sum_offdiag + Sum_diag - B*N*S(1),  S(1)=3.216328778.
//
// Occupancy design: 256 threads/block (8 warps), 1 row x 2 packed cols per
// thread, 32 iterations; ~32 regs -> 8 blocks/SM reg-limit, single wave at
// 7.13 blocks/SM, ~57 warps/SM resident. Staging spread over all 256
// threads. Deterministic reduction: fixed-point s64 atomicAdd.

#define NTHREADS 256
#define TILE 128
#define SCALE 1048576.0   // 2^20 fixed-point

__device__ unsigned long long g_isum;   // zero-init; reset by elected last block
__device__ unsigned int g_count;

typedef unsigned long long u64;

__device__ __forceinline__ u64 pk2(float lo, float hi) {
    u64 r; asm("mov.b64 %0, {%1, %2};" : "=l"(r) : "f"(lo), "f"(hi)); return r;
}
__device__ __forceinline__ void upk2(u64 v, float& lo, float& hi) {
    asm("mov.b64 {%0, %1}, %2;" : "=f"(lo), "=f"(hi) : "l"(v));
}
__device__ __forceinline__ u64 f2add(u64 a, u64 b) {
    u64 r; asm("add.rn.f32x2 %0, %1, %2;" : "=l"(r) : "l"(a), "l"(b)); return r;
}
__device__ __forceinline__ u64 f2mul(u64 a, u64 b) {
    u64 r; asm("mul.rn.f32x2 %0, %1, %2;" : "=l"(r) : "l"(a), "l"(b)); return r;
}
__device__ __forceinline__ u64 f2fma(u64 a, u64 b, u64 c) {
    u64 r; asm("fma.rn.f32x2 %0, %1, %2, %3;" : "=l"(r) : "l"(a), "l"(b), "l"(c)); return r;
}
__device__ __forceinline__ float ex2a(float x) {
    float r; asm("ex2.approx.f32 %0, %1;" : "=f"(r) : "f"(x)); return r;
}
__device__ __forceinline__ float rcpa(float x) {
    float r; asm("rcp.approx.f32 %0, %1;" : "=f"(r) : "f"(x)); return r;
}

__global__ __launch_bounds__(NTHREADS, 8) void lddt_kernel(
    const float* __restrict__ x,   // [B, N, 3]
    const float* __restrict__ g,   // [B, N, 3]
    float* __restrict__ out,
    int N, int tilesPerBatch, int T, int nUnits,
    double invCount, double diagTerm)
{
    // 64 column-pairs x 6 attrs (pre-negated, f32x2-packed), 48B record ->
    // three 16B-aligned LDS.128 per pair.
    __shared__ __align__(16) u64 scolp[TILE / 2][6];
    __shared__ float warpSums[NTHREADS / 32];

    const int tile = blockIdx.x;
    const int b = tile / tilesPerBatch;
    int rem = tile % tilesPerBatch;
    // Closed-form triangular decode (ti <= tj).
    int ti;
    {
        float tf = (float)T;
        ti = (int)floorf(tf + 0.5f - sqrtf((tf + 0.5f) * (tf + 0.5f) - 2.0f * (float)rem));
        while (ti > 0 && rem < ti * T - (ti * (ti - 1)) / 2) ti--;
        while (rem >= (ti + 1) * T - ((ti + 1) * ti) / 2) ti++;
    }
    const int rowOff = ti * T - (ti * (ti - 1)) / 2;
    const int tj = ti + (rem - rowOff);

    const int t = threadIdx.x;
    const long rowBase = (long)(b * N + ti * TILE) * 3;
    const long colBase = (long)(b * N + tj * TILE) * 3;

    // Stage negated, packed column coords — spread across all 256 threads.
    // 64 pairs x 6 attrs = 384 u64 records; each thread builds <= 2.
    for (int idx = t; idx < (TILE / 2) * 6; idx += NTHREADS) {
        const int p = idx / 6;
        const int a = idx % 6;
        const float* src = (a < 3) ? (x + colBase) : (g + colBase);
        const int c = (a < 3) ? a : (a - 3);
        float lo = src[(2 * p) * 3 + c];
        float hi = src[(2 * p + 1) * 3 + c];
        scolp[p][a] = pk2(-lo, -hi);
    }

    // Row r = t & 127 (register-resident, broadcast-packed);
    // column-pairs p = (t>>7) + 2k, k = 0..31 (warp-uniform -> LDS broadcast).
    const int r = t & 127;
    const int q = t >> 7;

    const float* rx = x + rowBase + r * 3;
    const float* rg = g + rowBase + r * 3;
    const float rx0 = rx[0], rx1 = rx[1], rx2 = rx[2];
    const float rg0 = rg[0], rg1 = rg[1], rg2 = rg[2];
    const u64 AX = pk2(rx0, rx0), AY = pk2(rx1, rx1), AZ = pk2(rx2, rx2);
    const u64 GX = pk2(rg0, rg0), GY = pk2(rg1, rg1), GZ = pk2(rg2, rg2);
    __syncthreads();

    // Q(u) = 1 + s1 u + s2 u^2 + s3 u^3 + s4 u^4 ; numerator u*Q'(u).
    const float S1 = 66.35420923f, S2 = 678.6088038f, S3 = 2039.582176f, S4 = 1808.042414f;
    const u64 S1v = pk2(S1, S1), S2v = pk2(S2, S2), S3v = pk2(S3, S3), S4v = pk2(S4, S4);
    const u64 C1v = S1v;
    const u64 C2v = pk2(2 * S2, 2 * S2);
    const u64 C3v = pk2(3 * S3, 3 * S3);
    const u64 C4v = pk2(4 * S4, 4 * S4);
    const u64 ONEv = pk2(1.0f, 1.0f);
    const u64 NEG1 = pk2(-1.0f, -1.0f);
    const float NL2E = -1.44269504f;                  // -log2(e)

    u64 accv = pk2(0.0f, 0.0f);

    // Branch-free, unmasked mainloop — identical for all tiles.
#pragma unroll 4
    for (int k = 0; k < 32; k++) {
        const int p = q + 2 * k;
        const ulonglong2* sp = (const ulonglong2*)&scolp[p][0];
        const ulonglong2 v0 = sp[0];   // {-bx, -by}
        const ulonglong2 v1 = sp[1];   // {-bz, -hx}
        const ulonglong2 v2 = sp[2];   // {-hy, -hz}

        u64 dxx = f2add(AX, v0.x), dxy = f2add(AY, v0.y), dxz = f2add(AZ, v1.x);
        u64 dgx = f2add(GX, v1.y), dgy = f2add(GY, v2.x), dgz = f2add(GZ, v2.y);
        u64 dx2 = f2fma(dxz, dxz, f2fma(dxy, dxy, f2mul(dxx, dxx)));
        u64 dg2 = f2fma(dgz, dgz, f2fma(dgy, dgy, f2mul(dgx, dgx)));
        u64 hv = f2fma(dx2, NEG1, dg2);               // dg2 - dx2 per lane

        float h0, h1; upk2(hv, h0, h1);
        float u0 = ex2a(fabsf(h0) * NL2E);            // exp(-|h|); underflow->0 exact
        float u1 = ex2a(fabsf(h1) * NL2E);
        u64 u = pk2(u0, u1);

        u64 Qp = f2fma(f2fma(f2fma(C4v, u, C3v), u, C2v), u, C1v);
        u64 Q  = f2fma(f2fma(f2fma(f2fma(S4v, u, S3v), u, S2v), u, S1v), u, ONEv);
        u64 P  = f2mul(u, Qp);
        float q0, q1; upk2(Q, q0, q1);
        u64 R = pk2(rcpa(q0), rcpa(q1));
        accv = f2fma(P, R, accv);
    }

    float a0, a1; upk2(accv, a0, a1);
    float acc = a0 + a1;

#pragma unroll
    for (int off = 16; off > 0; off >>= 1)
        acc += __shfl_down_sync(0xFFFFFFFFu, acc, off);
    if ((t & 31) == 0) warpSums[t >> 5] = acc;
    __syncthreads();

    if (t == 0) {
        float blockSum = 0.0f;
#pragma unroll
        for (int w = 0; w < NTHREADS / 32; w++) blockSum += warpSums[w];
        // Off-diagonal tiles count twice (symmetry); diagonal tiles once.
        double w = (ti == tj) ? 1.0 : 2.0;
        // Fixed-point accumulate: integer adds associative -> deterministic.
        long long qv = __double2ll_rn((double)blockSum * w * SCALE);
        atomicAdd(&g_isum, (unsigned long long)qv);
        __threadfence();
        unsigned int old = atomicAdd(&g_count, 1u);
        if (old == (unsigned int)(nUnits - 1)) {
            __threadfence();
            unsigned long long tot = *((volatile unsigned long long*)&g_isum);
            double s = (double)(long long)tot * (1.0 / SCALE);
            // sum_{l!=m} S = s - B*N*S(1); eps carries the 0.25 factor.
            out[0] = (float)(1.0 - 0.25 * (s - diagTerm) * invCount);
            g_isum = 0ULL;          // reset for next graph replay
            g_count = 0u;
        }
    }
}

extern "C" void kernel_launch(void* const* d_in, const int* in_sizes, int n_in,
                              void* d_out, int out_size)
{
    const float* x = (const float*)d_in[0];   // x_l   [B,N,3] f32
    const float* g = (const float*)d_in[1];   // xGT_l [B,N,3] f32
    // d_in[2]/d_in[3] (is_dna/is_rna) provably unused: c_lm == ~eye.

    const int B = 2;
    const int N = in_sizes[0] / (3 * B);        // 4096
    const int T = N / TILE;                     // 32
    const int tilesPerBatch = T * (T + 1) / 2;  // 528
    const int nUnits = B * tilesPerBatch;       // 1056 full tiles

    float* out = (float*)d_out;
    double invCount = 1.0 / ((double)B * (double)N * (double)(N - 1));
    // S(1) = sig(.5)+sig(1)+sig(2)+sig(4), the d=0 diagonal contribution.
    double diagTerm = (double)B * (double)N * 3.216328778234624;

    lddt_kernel<<<nUnits, NTHREADS>>>(x, g, out, N, tilesPerBatch, T, nUnits,
                                      invCount, diagTerm);
}